// round 1
// baseline (speedup 1.0000x reference)
#include <cuda_runtime.h>
#include <math.h>

#define Bb 8
#define Hh 16
#define Nn 512
#define Dk 64
#define Dm 1024

// ---------------- scratch (device globals — no allocations) ----------------
__device__ float g_q[Bb*Hh*Nn*Dk];            // 16 MB, layout (b,h,n,d)
__device__ float g_k[Bb*Hh*Nn*Dk];            // 16 MB
__device__ float g_v[Bb*Hh*Nn*Dk];            // 16 MB
__device__ float g_bias[(size_t)Bb*Hh*Nn*Nn]; // 537 MB, layout (b,h,q,k): log(clip(relu(g),1e-6))
__device__ float g_attn[Bb*Nn*Hh*Dk];         // 16 MB, layout (b,n, h*64+d)

// ---------------------------------------------------------------------------
// SGEMM: C[M=4096, N=1024] = A[4096,1024] @ W[1024,1024]^T + bias[N]
// BM=BN=128, BK=8, 256 threads, 8x8 micro-tile per thread.
// remap==1: scatter output to (b,h,n,d) layout for Q/K/V.
// ---------------------------------------------------------------------------
__global__ __launch_bounds__(256) void sgemm_tn(const float* __restrict__ A,
                                                const float* __restrict__ W,
                                                const float* __restrict__ bias,
                                                float* __restrict__ C,
                                                int remap) {
    __shared__ float As[8][128];
    __shared__ float Bs[8][128];
    int tid = threadIdx.x;
    int tx = tid & 15, ty = tid >> 4;
    int m0 = blockIdx.y * 128, n0 = blockIdx.x * 128;
    int lr = tid >> 1;            // 0..127
    int lc = (tid & 1) * 4;       // 0 or 4
    const float* Ap = A + (size_t)(m0 + lr) * 1024 + lc;
    const float* Wp = W + (size_t)(n0 + lr) * 1024 + lc;

    float acc[8][8];
#pragma unroll
    for (int i = 0; i < 8; i++)
#pragma unroll
        for (int j = 0; j < 8; j++) acc[i][j] = 0.f;

    for (int kt = 0; kt < 128; kt++) {
        float4 av = *(const float4*)(Ap + kt * 8);
        float4 wv = *(const float4*)(Wp + kt * 8);
        __syncthreads();   // previous iteration's reads done before overwrite
        As[lc + 0][lr] = av.x; As[lc + 1][lr] = av.y;
        As[lc + 2][lr] = av.z; As[lc + 3][lr] = av.w;
        Bs[lc + 0][lr] = wv.x; Bs[lc + 1][lr] = wv.y;
        Bs[lc + 2][lr] = wv.z; Bs[lc + 3][lr] = wv.w;
        __syncthreads();
#pragma unroll
        for (int kk = 0; kk < 8; kk++) {
            float4 a0 = *(const float4*)&As[kk][ty * 4];
            float4 a1 = *(const float4*)&As[kk][64 + ty * 4];
            float4 b0 = *(const float4*)&Bs[kk][tx * 4];
            float4 b1 = *(const float4*)&Bs[kk][64 + tx * 4];
            float af[8] = {a0.x, a0.y, a0.z, a0.w, a1.x, a1.y, a1.z, a1.w};
            float bf[8] = {b0.x, b0.y, b0.z, b0.w, b1.x, b1.y, b1.z, b1.w};
#pragma unroll
            for (int i = 0; i < 8; i++)
#pragma unroll
                for (int j = 0; j < 8; j++)
                    acc[i][j] += af[i] * bf[j];
        }
    }

    // epilogue: add bias, write (optionally remapped to (b,h,n,d))
#pragma unroll
    for (int i = 0; i < 8; i++) {
        int mrow = m0 + ((i < 4) ? (ty * 4 + i) : (64 + ty * 4 + (i - 4)));
#pragma unroll
        for (int jq = 0; jq < 2; jq++) {
            int ncol = n0 + ((jq == 0) ? (tx * 4) : (64 + tx * 4));
            float4 v;
            v.x = acc[i][jq * 4 + 0] + bias[ncol + 0];
            v.y = acc[i][jq * 4 + 1] + bias[ncol + 1];
            v.z = acc[i][jq * 4 + 2] + bias[ncol + 2];
            v.w = acc[i][jq * 4 + 3] + bias[ncol + 3];
            if (remap) {
                int bb = mrow >> 9, n = mrow & 511, hh = ncol >> 6, d = ncol & 63;
                *(float4*)&C[(((size_t)bb * Hh + hh) * Nn + n) * Dk + d] = v;
            } else {
                *(float4*)&C[(size_t)mrow * 1024 + ncol] = v;
            }
        }
    }
}

// ---------------------------------------------------------------------------
// Geometry bias: for each (b, i, j) pair compute the 64-dim trig embedding and
// the 16-head einsum with Wg in one shot; write log(max(g, 1e-6)) to g_bias.
// Block = one (b, i); 256 threads loop over j.
// ---------------------------------------------------------------------------
__global__ __launch_bounds__(256) void geo_bias_kernel(const float* __restrict__ boxes,
                                                       const float* __restrict__ Wg,
                                                       const float* __restrict__ bg) {
    __shared__ float Wsin[32][16];   // Wsin[idx][h] = Wg[h][idx]
    __shared__ float Wcos[32][16];   // Wcos[idx][h] = Wg[h][32+idx]
    __shared__ float bgs[16];
    int i = blockIdx.x, b = blockIdx.y;
    int tid = threadIdx.x;

    for (int t = tid; t < Hh * 64; t += 256) {
        int h = t >> 6, d = t & 63;
        float w = Wg[h * 64 + d];
        if (d < 32) Wsin[d][h] = w;
        else        Wcos[d - 32][h] = w;
    }
    if (tid < 16) bgs[tid] = bg[tid];

    const float* pbi = boxes + ((size_t)b * Nn + i) * 4;
    float xi0 = pbi[0], yi0 = pbi[1], xi1 = pbi[2], yi1 = pbi[3];
    float cxi = 0.5f * (xi0 + xi1), cyi = 0.5f * (yi0 + yi1);
    float wi = xi1 - xi0 + 1.0f, hi = yi1 - yi0 + 1.0f;
    float lwi = __logf(wi), lhi = __logf(hi);
    __syncthreads();

    const float dm[8] = {1.0f, 0.421696503429f, 0.177827941004f, 0.0749894209332f,
                         0.0316227766017f, 0.0133352143216f, 0.00562341325190f,
                         0.00237137370566f};

    for (int j = tid; j < Nn; j += 256) {
        const float* pbj = boxes + ((size_t)b * Nn + j) * 4;
        float xj0 = pbj[0], yj0 = pbj[1], xj1 = pbj[2], yj1 = pbj[3];
        float cxj = 0.5f * (xj0 + xj1), cyj = 0.5f * (yj0 + yj1);
        float wj = xj1 - xj0 + 1.0f, hj = yj1 - yj0 + 1.0f;

        float pos[4];
        pos[0] = __logf(fmaxf(fabsf((cxi - cxj) / wi), 1e-3f));
        pos[1] = __logf(fmaxf(fabsf((cyi - cyj) / hi), 1e-3f));
        pos[2] = lwi - __logf(wj);
        pos[3] = lhi - __logf(hj);

        float sv[32], cv[32];
#pragma unroll
        for (int c = 0; c < 4; c++) {
            float base = 100.0f * pos[c];
#pragma unroll
            for (int f = 0; f < 8; f++)
                __sincosf(base * dm[f], &sv[c * 8 + f], &cv[c * 8 + f]);
        }

        float acc[16];
#pragma unroll
        for (int h = 0; h < 16; h++) acc[h] = bgs[h];
#pragma unroll
        for (int idx = 0; idx < 32; idx++) {
            float s = sv[idx], c = cv[idx];
#pragma unroll
            for (int hq = 0; hq < 4; hq++) {
                float4 ws = *(const float4*)&Wsin[idx][hq * 4];
                float4 wc = *(const float4*)&Wcos[idx][hq * 4];
                acc[hq * 4 + 0] += s * ws.x + c * wc.x;
                acc[hq * 4 + 1] += s * ws.y + c * wc.y;
                acc[hq * 4 + 2] += s * ws.z + c * wc.z;
                acc[hq * 4 + 3] += s * ws.w + c * wc.w;
            }
        }
#pragma unroll
        for (int h = 0; h < 16; h++) {
            // relu then clip(1e-6) then log  ==  log(max(acc, 1e-6))
            g_bias[(((size_t)b * Hh + h) * Nn + i) * Nn + j] =
                __logf(fmaxf(acc[h], 1e-6f));
        }
    }
}

// ---------------------------------------------------------------------------
// Attention: one block per (b*h, 32-query tile). Full 512-wide score rows in
// smem, two-pass softmax, then PV. K/V tiles stored with stride-65 padding.
// Dynamic smem: Qs(2048) + KVs(64*65) + S(32*512) + rowsum(32) = 90496 B.
// ---------------------------------------------------------------------------
__global__ __launch_bounds__(256) void attn_kernel() {
    extern __shared__ float sh[];
    float* Qs = sh;                      // [32][64]
    float* KVs = Qs + 32 * 64;           // [64][65] padded
    float* S = KVs + 64 * 65;            // [32][512]
    float* rowsum = S + 32 * 512;        // [32]

    int bh = blockIdx.y;
    int b = bh >> 4, h = bh & 15;
    int q0 = blockIdx.x * 32;
    const float* Qg = g_q + ((size_t)bh * Nn + q0) * Dk;
    const float* Kg = g_k + (size_t)bh * Nn * Dk;
    const float* Vg = g_v + (size_t)bh * Nn * Dk;
    const float* Bg = g_bias + ((size_t)bh * Nn + q0) * Nn;

    int tid = threadIdx.x;
    int ty = tid >> 5, tx = tid & 31;    // ty: q-row group (4 rows), tx: lane

    for (int i = tid; i < 32 * 16; i += 256)
        ((float4*)Qs)[i] = ((const float4*)Qg)[i];

    // ---- scores ----
    for (int kt = 0; kt < 8; kt++) {
        __syncthreads();
        for (int i = tid; i < 64 * 16; i += 256) {
            int r = i >> 4, c4 = (i & 15) * 4;
            float4 kv = ((const float4*)(Kg + (size_t)(kt * 64 + r) * Dk))[i & 15];
            KVs[r * 65 + c4 + 0] = kv.x;
            KVs[r * 65 + c4 + 1] = kv.y;
            KVs[r * 65 + c4 + 2] = kv.z;
            KVs[r * 65 + c4 + 3] = kv.w;
        }
        __syncthreads();
        float acc[4][2] = {{0.f,0.f},{0.f,0.f},{0.f,0.f},{0.f,0.f}};
#pragma unroll 8
        for (int d = 0; d < 64; d++) {
            float k0 = KVs[tx * 65 + d];
            float k1 = KVs[(tx + 32) * 65 + d];
#pragma unroll
            for (int qq = 0; qq < 4; qq++) {
                float qv = Qs[(ty * 4 + qq) * 64 + d];
                acc[qq][0] += qv * k0;
                acc[qq][1] += qv * k1;
            }
        }
#pragma unroll
        for (int qq = 0; qq < 4; qq++) {
            int qr = ty * 4 + qq;
            S[qr * 512 + kt * 64 + tx] =
                acc[qq][0] * 0.125f + Bg[(size_t)qr * Nn + kt * 64 + tx];
            S[qr * 512 + kt * 64 + tx + 32] =
                acc[qq][1] * 0.125f + Bg[(size_t)qr * Nn + kt * 64 + tx + 32];
        }
    }
    __syncthreads();

    // ---- softmax (each warp owns its 4 q rows) ----
#pragma unroll
    for (int qq = 0; qq < 4; qq++) {
        int qr = ty * 4 + qq;
        float m = -1e30f;
        for (int i = tx; i < 512; i += 32) m = fmaxf(m, S[qr * 512 + i]);
#pragma unroll
        for (int o = 16; o; o >>= 1) m = fmaxf(m, __shfl_xor_sync(0xffffffffu, m, o));
        float sum = 0.f;
        for (int i = tx; i < 512; i += 32) {
            float p = __expf(S[qr * 512 + i] - m);
            S[qr * 512 + i] = p;
            sum += p;
        }
#pragma unroll
        for (int o = 16; o; o >>= 1) sum += __shfl_xor_sync(0xffffffffu, sum, o);
        if (tx == 0) rowsum[qr] = sum;
    }
    __syncthreads();

    // ---- PV ----
    float oa[4][2] = {{0.f,0.f},{0.f,0.f},{0.f,0.f},{0.f,0.f}};
    for (int kt = 0; kt < 8; kt++) {
        __syncthreads();
        for (int i = tid; i < 64 * 16; i += 256) {
            int r = i >> 4, c4 = (i & 15) * 4;
            float4 vv = ((const float4*)(Vg + (size_t)(kt * 64 + r) * Dk))[i & 15];
            KVs[r * 65 + c4 + 0] = vv.x;
            KVs[r * 65 + c4 + 1] = vv.y;
            KVs[r * 65 + c4 + 2] = vv.z;
            KVs[r * 65 + c4 + 3] = vv.w;
        }
        __syncthreads();
#pragma unroll 8
        for (int r = 0; r < 64; r++) {
            float v0 = KVs[r * 65 + tx];
            float v1 = KVs[r * 65 + tx + 32];
#pragma unroll
            for (int qq = 0; qq < 4; qq++) {
                float p = S[(ty * 4 + qq) * 512 + kt * 64 + r];
                oa[qq][0] += p * v0;
                oa[qq][1] += p * v1;
            }
        }
    }

#pragma unroll
    for (int qq = 0; qq < 4; qq++) {
        int qr = ty * 4 + qq;
        float inv = 1.0f / rowsum[qr];
        size_t base = ((size_t)b * Nn + q0 + qr) * (size_t)Dm + (size_t)h * 64;
        g_attn[base + tx] = oa[qq][0] * inv;
        g_attn[base + tx + 32] = oa[qq][1] * inv;
    }
}

// ---------------------------------------------------------------------------
extern "C" void kernel_launch(void* const* d_in, const int* in_sizes, int n_in,
                              void* d_out, int out_size) {
    (void)in_sizes; (void)n_in; (void)out_size;
    const float* queries = (const float*)d_in[0];
    const float* keys    = (const float*)d_in[1];
    const float* values  = (const float*)d_in[2];
    const float* boxes   = (const float*)d_in[3];
    const float* Wq = (const float*)d_in[4];
    const float* bq = (const float*)d_in[5];
    const float* Wk = (const float*)d_in[6];
    const float* bk = (const float*)d_in[7];
    const float* Wv = (const float*)d_in[8];
    const float* bv = (const float*)d_in[9];
    const float* Wo = (const float*)d_in[10];
    const float* bo = (const float*)d_in[11];
    const float* Wg = (const float*)d_in[12];
    const float* bg = (const float*)d_in[13];
    float* out = (float*)d_out;

    float *dq = nullptr, *dk = nullptr, *dv = nullptr, *dattn = nullptr;
    cudaGetSymbolAddress((void**)&dq, g_q);
    cudaGetSymbolAddress((void**)&dk, g_k);
    cudaGetSymbolAddress((void**)&dv, g_v);
    cudaGetSymbolAddress((void**)&dattn, g_attn);

    size_t shbytes = (size_t)(32 * 64 + 64 * 65 + 32 * 512 + 32) * sizeof(float);
    cudaFuncSetAttribute(attn_kernel, cudaFuncAttributeMaxDynamicSharedMemorySize,
                         (int)shbytes);

    dim3 gemm_grid(Dm / 128, (Bb * Nn) / 128);   // (8, 32)

    // geometry bias first (independent of projections)
    geo_bias_kernel<<<dim3(Nn, Bb), 256>>>(boxes, Wg, bg);

    sgemm_tn<<<gemm_grid, 256>>>(queries, Wq, bq, dq, 1);
    sgemm_tn<<<gemm_grid, 256>>>(keys,    Wk, bk, dk, 1);
    sgemm_tn<<<gemm_grid, 256>>>(values,  Wv, bv, dv, 1);

    attn_kernel<<<dim3(Nn / 32, Bb * Hh), 256, shbytes>>>();

    sgemm_tn<<<gemm_grid, 256>>>(dattn, Wo, bo, out, 0);
}

// round 2
// speedup vs baseline: 1.0082x; 1.0082x over previous
#include <cuda_runtime.h>
#include <math.h>

#define Bb 8
#define Hh 16
#define Nn 512
#define Dk 64
#define Dm 1024

// ---------------- scratch (device globals — no allocations) ----------------
__device__ float g_q[Bb*Hh*Nn*Dk];            // 16 MB, layout (b,h,n,d)
__device__ float g_k[Bb*Hh*Nn*Dk];            // 16 MB
__device__ float g_v[Bb*Hh*Nn*Dk];            // 16 MB
__device__ float g_bias[(size_t)Bb*Hh*Nn*Nn]; // 537 MB, layout (b,h,q,k): log(clip(relu(g),1e-6))
__device__ float g_attn[Bb*Nn*Hh*Dk];         // 16 MB, layout (b,n, h*64+d)

// ---------------------------------------------------------------------------
// SGEMM: C[M=4096, N=1024] = A[4096,1024] @ W[1024,1024]^T + bias[N]
// BM=BN=128, BK=8, 256 threads, 8x8 micro-tile per thread.
// remap==1: scatter output to (b,h,n,d) layout for Q/K/V.
// ---------------------------------------------------------------------------
__global__ __launch_bounds__(256) void sgemm_tn(const float* __restrict__ A,
                                                const float* __restrict__ W,
                                                const float* __restrict__ bias,
                                                float* __restrict__ C,
                                                int remap) {
    __shared__ float As[8][128];
    __shared__ float Bs[8][128];
    int tid = threadIdx.x;
    int tx = tid & 15, ty = tid >> 4;
    int m0 = blockIdx.y * 128, n0 = blockIdx.x * 128;
    int lr = tid >> 1;            // 0..127
    int lc = (tid & 1) * 4;       // 0 or 4
    const float* Ap = A + (size_t)(m0 + lr) * 1024 + lc;
    const float* Wp = W + (size_t)(n0 + lr) * 1024 + lc;

    float acc[8][8];
#pragma unroll
    for (int i = 0; i < 8; i++)
#pragma unroll
        for (int j = 0; j < 8; j++) acc[i][j] = 0.f;

    for (int kt = 0; kt < 128; kt++) {
        float4 av = *(const float4*)(Ap + kt * 8);
        float4 wv = *(const float4*)(Wp + kt * 8);
        __syncthreads();   // previous iteration's reads done before overwrite
        As[lc + 0][lr] = av.x; As[lc + 1][lr] = av.y;
        As[lc + 2][lr] = av.z; As[lc + 3][lr] = av.w;
        Bs[lc + 0][lr] = wv.x; Bs[lc + 1][lr] = wv.y;
        Bs[lc + 2][lr] = wv.z; Bs[lc + 3][lr] = wv.w;
        __syncthreads();
#pragma unroll
        for (int kk = 0; kk < 8; kk++) {
            float4 a0 = *(const float4*)&As[kk][ty * 4];
            float4 a1 = *(const float4*)&As[kk][64 + ty * 4];
            float4 b0 = *(const float4*)&Bs[kk][tx * 4];
            float4 b1 = *(const float4*)&Bs[kk][64 + tx * 4];
            float af[8] = {a0.x, a0.y, a0.z, a0.w, a1.x, a1.y, a1.z, a1.w};
            float bf[8] = {b0.x, b0.y, b0.z, b0.w, b1.x, b1.y, b1.z, b1.w};
#pragma unroll
            for (int i = 0; i < 8; i++)
#pragma unroll
                for (int j = 0; j < 8; j++)
                    acc[i][j] += af[i] * bf[j];
        }
    }

    // epilogue: add bias, write (optionally remapped to (b,h,n,d))
#pragma unroll
    for (int i = 0; i < 8; i++) {
        int mrow = m0 + ((i < 4) ? (ty * 4 + i) : (64 + ty * 4 + (i - 4)));
#pragma unroll
        for (int jq = 0; jq < 2; jq++) {
            int ncol = n0 + ((jq == 0) ? (tx * 4) : (64 + tx * 4));
            float4 v;
            v.x = acc[i][jq * 4 + 0] + bias[ncol + 0];
            v.y = acc[i][jq * 4 + 1] + bias[ncol + 1];
            v.z = acc[i][jq * 4 + 2] + bias[ncol + 2];
            v.w = acc[i][jq * 4 + 3] + bias[ncol + 3];
            if (remap) {
                int bb = mrow >> 9, n = mrow & 511, hh = ncol >> 6, d = ncol & 63;
                *(float4*)&C[(((size_t)bb * Hh + hh) * Nn + n) * Dk + d] = v;
            } else {
                *(float4*)&C[(size_t)mrow * 1024 + ncol] = v;
            }
        }
    }
}

// ---------------------------------------------------------------------------
// Geometry bias: for each (b, i, j) pair compute the 64-dim trig embedding and
// the 16-head einsum with Wg in one shot; write log(max(g, 1e-6)) to g_bias.
// Block = one (b, i); 256 threads loop over j.
// ---------------------------------------------------------------------------
__global__ __launch_bounds__(256) void geo_bias_kernel(const float* __restrict__ boxes,
                                                       const float* __restrict__ Wg,
                                                       const float* __restrict__ bg) {
    __shared__ float Wsin[32][16];   // Wsin[idx][h] = Wg[h][idx]
    __shared__ float Wcos[32][16];   // Wcos[idx][h] = Wg[h][32+idx]
    __shared__ float bgs[16];
    int i = blockIdx.x, b = blockIdx.y;
    int tid = threadIdx.x;

    for (int t = tid; t < Hh * 64; t += 256) {
        int h = t >> 6, d = t & 63;
        float w = Wg[h * 64 + d];
        if (d < 32) Wsin[d][h] = w;
        else        Wcos[d - 32][h] = w;
    }
    if (tid < 16) bgs[tid] = bg[tid];

    const float* pbi = boxes + ((size_t)b * Nn + i) * 4;
    float xi0 = pbi[0], yi0 = pbi[1], xi1 = pbi[2], yi1 = pbi[3];
    float cxi = 0.5f * (xi0 + xi1), cyi = 0.5f * (yi0 + yi1);
    float wi = xi1 - xi0 + 1.0f, hi = yi1 - yi0 + 1.0f;
    float lwi = __logf(wi), lhi = __logf(hi);
    __syncthreads();

    const float dm[8] = {1.0f, 0.421696503429f, 0.177827941004f, 0.0749894209332f,
                         0.0316227766017f, 0.0133352143216f, 0.00562341325190f,
                         0.00237137370566f};

    for (int j = tid; j < Nn; j += 256) {
        const float* pbj = boxes + ((size_t)b * Nn + j) * 4;
        float xj0 = pbj[0], yj0 = pbj[1], xj1 = pbj[2], yj1 = pbj[3];
        float cxj = 0.5f * (xj0 + xj1), cyj = 0.5f * (yj0 + yj1);
        float wj = xj1 - xj0 + 1.0f, hj = yj1 - yj0 + 1.0f;

        float pos[4];
        pos[0] = __logf(fmaxf(fabsf((cxi - cxj) / wi), 1e-3f));
        pos[1] = __logf(fmaxf(fabsf((cyi - cyj) / hi), 1e-3f));
        pos[2] = lwi - __logf(wj);
        pos[3] = lhi - __logf(hj);

        float sv[32], cv[32];
#pragma unroll
        for (int c = 0; c < 4; c++) {
            float base = 100.0f * pos[c];
#pragma unroll
            for (int f = 0; f < 8; f++)
                __sincosf(base * dm[f], &sv[c * 8 + f], &cv[c * 8 + f]);
        }

        float acc[16];
#pragma unroll
        for (int h = 0; h < 16; h++) acc[h] = bgs[h];
#pragma unroll
        for (int idx = 0; idx < 32; idx++) {
            float s = sv[idx], c = cv[idx];
#pragma unroll
            for (int hq = 0; hq < 4; hq++) {
                float4 ws = *(const float4*)&Wsin[idx][hq * 4];
                float4 wc = *(const float4*)&Wcos[idx][hq * 4];
                acc[hq * 4 + 0] += s * ws.x + c * wc.x;
                acc[hq * 4 + 1] += s * ws.y + c * wc.y;
                acc[hq * 4 + 2] += s * ws.z + c * wc.z;
                acc[hq * 4 + 3] += s * ws.w + c * wc.w;
            }
        }
#pragma unroll
        for (int h = 0; h < 16; h++) {
            // relu then clip(1e-6) then log  ==  log(max(acc, 1e-6))
            g_bias[(((size_t)b * Hh + h) * Nn + i) * Nn + j] =
                __logf(fmaxf(acc[h], 1e-6f));
        }
    }
}

// ---------------------------------------------------------------------------
// Attention: one block per (b*h, 32-query tile). Full 512-wide score rows in
// smem, two-pass softmax, then PV. K/V tiles stored with stride-65 padding.
// Dynamic smem: Qs(2048) + KVs(64*65) + S(32*512) + rowsum(32) = 90496 B.
// ---------------------------------------------------------------------------
__global__ __launch_bounds__(256) void attn_kernel() {
    extern __shared__ float sh[];
    float* Qs = sh;                      // [32][64]
    float* KVs = Qs + 32 * 64;           // [64][65] padded
    float* S = KVs + 64 * 65;            // [32][512]
    float* rowsum = S + 32 * 512;        // [32]

    int bh = blockIdx.y;
    int b = bh >> 4, h = bh & 15;
    int q0 = blockIdx.x * 32;
    const float* Qg = g_q + ((size_t)bh * Nn + q0) * Dk;
    const float* Kg = g_k + (size_t)bh * Nn * Dk;
    const float* Vg = g_v + (size_t)bh * Nn * Dk;
    const float* Bg = g_bias + ((size_t)bh * Nn + q0) * Nn;

    int tid = threadIdx.x;
    int ty = tid >> 5, tx = tid & 31;    // ty: q-row group (4 rows), tx: lane

    for (int i = tid; i < 32 * 16; i += 256)
        ((float4*)Qs)[i] = ((const float4*)Qg)[i];

    // ---- scores ----
    for (int kt = 0; kt < 8; kt++) {
        __syncthreads();
        for (int i = tid; i < 64 * 16; i += 256) {
            int r = i >> 4, c4 = (i & 15) * 4;
            float4 kv = ((const float4*)(Kg + (size_t)(kt * 64 + r) * Dk))[i & 15];
            KVs[r * 65 + c4 + 0] = kv.x;
            KVs[r * 65 + c4 + 1] = kv.y;
            KVs[r * 65 + c4 + 2] = kv.z;
            KVs[r * 65 + c4 + 3] = kv.w;
        }
        __syncthreads();
        float acc[4][2] = {{0.f,0.f},{0.f,0.f},{0.f,0.f},{0.f,0.f}};
#pragma unroll 8
        for (int d = 0; d < 64; d++) {
            float k0 = KVs[tx * 65 + d];
            float k1 = KVs[(tx + 32) * 65 + d];
#pragma unroll
            for (int qq = 0; qq < 4; qq++) {
                float qv = Qs[(ty * 4 + qq) * 64 + d];
                acc[qq][0] += qv * k0;
                acc[qq][1] += qv * k1;
            }
        }
#pragma unroll
        for (int qq = 0; qq < 4; qq++) {
            int qr = ty * 4 + qq;
            S[qr * 512 + kt * 64 + tx] =
                acc[qq][0] * 0.125f + Bg[(size_t)qr * Nn + kt * 64 + tx];
            S[qr * 512 + kt * 64 + tx + 32] =
                acc[qq][1] * 0.125f + Bg[(size_t)qr * Nn + kt * 64 + tx + 32];
        }
    }
    __syncthreads();

    // ---- softmax (each warp owns its 4 q rows) ----
#pragma unroll
    for (int qq = 0; qq < 4; qq++) {
        int qr = ty * 4 + qq;
        float m = -1e30f;
        for (int i = tx; i < 512; i += 32) m = fmaxf(m, S[qr * 512 + i]);
#pragma unroll
        for (int o = 16; o; o >>= 1) m = fmaxf(m, __shfl_xor_sync(0xffffffffu, m, o));
        float sum = 0.f;
        for (int i = tx; i < 512; i += 32) {
            float p = __expf(S[qr * 512 + i] - m);
            S[qr * 512 + i] = p;
            sum += p;
        }
#pragma unroll
        for (int o = 16; o; o >>= 1) sum += __shfl_xor_sync(0xffffffffu, sum, o);
        if (tx == 0) rowsum[qr] = sum;
    }
    __syncthreads();

    // ---- PV ----
    float oa[4][2] = {{0.f,0.f},{0.f,0.f},{0.f,0.f},{0.f,0.f}};
    for (int kt = 0; kt < 8; kt++) {
        __syncthreads();
        for (int i = tid; i < 64 * 16; i += 256) {
            int r = i >> 4, c4 = (i & 15) * 4;
            float4 vv = ((const float4*)(Vg + (size_t)(kt * 64 + r) * Dk))[i & 15];
            KVs[r * 65 + c4 + 0] = vv.x;
            KVs[r * 65 + c4 + 1] = vv.y;
            KVs[r * 65 + c4 + 2] = vv.z;
            KVs[r * 65 + c4 + 3] = vv.w;
        }
        __syncthreads();
#pragma unroll 8
        for (int r = 0; r < 64; r++) {
            float v0 = KVs[r * 65 + tx];
            float v1 = KVs[r * 65 + tx + 32];
#pragma unroll
            for (int qq = 0; qq < 4; qq++) {
                float p = S[(ty * 4 + qq) * 512 + kt * 64 + r];
                oa[qq][0] += p * v0;
                oa[qq][1] += p * v1;
            }
        }
    }

#pragma unroll
    for (int qq = 0; qq < 4; qq++) {
        int qr = ty * 4 + qq;
        float inv = 1.0f / rowsum[qr];
        size_t base = ((size_t)b * Nn + q0 + qr) * (size_t)Dm + (size_t)h * 64;
        g_attn[base + tx] = oa[qq][0] * inv;
        g_attn[base + tx + 32] = oa[qq][1] * inv;
    }
}

// ---------------------------------------------------------------------------
extern "C" void kernel_launch(void* const* d_in, const int* in_sizes, int n_in,
                              void* d_out, int out_size) {
    (void)in_sizes; (void)n_in; (void)out_size;
    const float* queries = (const float*)d_in[0];
    const float* keys    = (const float*)d_in[1];
    const float* values  = (const float*)d_in[2];
    const float* boxes   = (const float*)d_in[3];
    const float* Wq = (const float*)d_in[4];
    const float* bq = (const float*)d_in[5];
    const float* Wk = (const float*)d_in[6];
    const float* bk = (const float*)d_in[7];
    const float* Wv = (const float*)d_in[8];
    const float* bv = (const float*)d_in[9];
    const float* Wo = (const float*)d_in[10];
    const float* bo = (const float*)d_in[11];
    const float* Wg = (const float*)d_in[12];
    const float* bg = (const float*)d_in[13];
    float* out = (float*)d_out;

    float *dq = nullptr, *dk = nullptr, *dv = nullptr, *dattn = nullptr;
    cudaGetSymbolAddress((void**)&dq, g_q);
    cudaGetSymbolAddress((void**)&dk, g_k);
    cudaGetSymbolAddress((void**)&dv, g_v);
    cudaGetSymbolAddress((void**)&dattn, g_attn);

    size_t shbytes = (size_t)(32 * 64 + 64 * 65 + 32 * 512 + 32) * sizeof(float);
    cudaFuncSetAttribute(attn_kernel, cudaFuncAttributeMaxDynamicSharedMemorySize,
                         (int)shbytes);

    dim3 gemm_grid(Dm / 128, (Bb * Nn) / 128);   // (8, 32)

    // geometry bias first (independent of projections)
    geo_bias_kernel<<<dim3(Nn, Bb), 256>>>(boxes, Wg, bg);

    sgemm_tn<<<gemm_grid, 256>>>(queries, Wq, bq, dq, 1);
    sgemm_tn<<<gemm_grid, 256>>>(keys,    Wk, bk, dk, 1);
    sgemm_tn<<<gemm_grid, 256>>>(values,  Wv, bv, dv, 1);

    attn_kernel<<<dim3(Nn / 32, Bb * Hh), 256, shbytes>>>();

    sgemm_tn<<<gemm_grid, 256>>>(dattn, Wo, bo, out, 0);
}